// round 16
// baseline (speedup 1.0000x reference)
#include <cuda_runtime.h>
#include <cuda_bf16.h>
#include <math.h>

#define BB 64
#define LL 1024
#define HH 64
#define H2 128
#define VV 32000
#define TOK 64
#define HPAD 68

// Scratch (device globals; no allocation allowed; zero-initialized)
__device__ float  g_kall[BB * LL * HH];   // 16 MB
__device__ float4 g_meta[BB * LL];        // (rinv, 0.16*kk, D(t,t+1), D(t,t+2))
__device__ float4 g_dx[BB * LL];          // (D(t,t+3), D(t,t+4), D(t,t+5), 0)
__device__ float  g_r2[BB * HH];

// ---------------------------------------------------------------------------
// Kernel 1: per-token front-end (round-12 WIN config) — unchanged.
// ---------------------------------------------------------------------------
__global__ void __launch_bounds__(256, 2) k1_frontend(
        const int* __restrict__ seq, const float* __restrict__ embed,
        const float* __restrict__ W1, const float* __restrict__ b1,
        const float* __restrict__ W2, const float* __restrict__ b2,
        const float* __restrict__ gamma, const float* __restrict__ beta,
        const float* __restrict__ kpW) {
    extern __shared__ float sm[];
    float* h_sm = sm;                      // TOK * HPAD
    float* u_sm = h_sm + TOK * HPAD;       // 64 * 128
    float* wbuf = u_sm + TOK * H2;         // 8192 (W1 / W2 / kpW)
    float* b1s  = wbuf + HH * H2;          // 128
    float* b2s  = b1s + H2;                // 64
    float* gsm  = b2s + HH;                // 64
    float* bsm  = gsm + HH;                // 64

    const int tid  = threadIdx.x;
    const int tok0 = blockIdx.x * TOK;

    if (tid < H2) b1s[tid] = b1[tid];
    if (tid < HH) { b2s[tid] = b2[tid]; gsm[tid] = gamma[tid]; bsm[tid] = beta[tid]; }
    {
        const float4* w4 = (const float4*)W1;
        float4* d4 = (float4*)wbuf;
        #pragma unroll
        for (int k = 0; k < 8; k++) d4[tid + 256 * k] = w4[tid + 256 * k];
    }
    #pragma unroll
    for (int k = 0; k < 16; k++) {
        int idx = tid + 256 * k;
        int t = idx >> 6, j = idx & 63;
        int row = seq[tok0 + t];
        h_sm[t * HPAD + j] = embed[row * HH + j];
    }
    __syncthreads();

    const int tt = tid >> 4;
    const int ct = tid & 15;

    // GEMM1
    {
        const int r0 = tt * 4, c0 = ct * 8;
        float acc[4][8];
        #pragma unroll
        for (int r = 0; r < 4; r++)
            #pragma unroll
            for (int c = 0; c < 8; c++) acc[r][c] = 0.f;
        #pragma unroll 2
        for (int j4 = 0; j4 < HH; j4 += 4) {
            float hv[4][4];
            #pragma unroll
            for (int r = 0; r < 4; r++)
                *(float4*)hv[r] = *(const float4*)&h_sm[(r0 + r) * HPAD + j4];
            #pragma unroll
            for (int jj = 0; jj < 4; jj++) {
                float4 wA = *(const float4*)&wbuf[(j4 + jj) * H2 + c0];
                float4 wB = *(const float4*)&wbuf[(j4 + jj) * H2 + c0 + 4];
                #pragma unroll
                for (int r = 0; r < 4; r++) {
                    float hvv = hv[r][jj];
                    acc[r][0] = fmaf(hvv, wA.x, acc[r][0]);
                    acc[r][1] = fmaf(hvv, wA.y, acc[r][1]);
                    acc[r][2] = fmaf(hvv, wA.z, acc[r][2]);
                    acc[r][3] = fmaf(hvv, wA.w, acc[r][3]);
                    acc[r][4] = fmaf(hvv, wB.x, acc[r][4]);
                    acc[r][5] = fmaf(hvv, wB.y, acc[r][5]);
                    acc[r][6] = fmaf(hvv, wB.z, acc[r][6]);
                    acc[r][7] = fmaf(hvv, wB.w, acc[r][7]);
                }
            }
        }
        #pragma unroll
        for (int r = 0; r < 4; r++)
            #pragma unroll
            for (int c = 0; c < 8; c++)
                u_sm[(r0 + r) * H2 + c0 + c] = fmaxf(acc[r][c] + b1s[c0 + c], 0.f);
    }
    __syncthreads();

    // load W2 over W1
    {
        const float4* w4 = (const float4*)W2;
        float4* d4 = (float4*)wbuf;
        #pragma unroll
        for (int k = 0; k < 8; k++) d4[tid + 256 * k] = w4[tid + 256 * k];
    }
    __syncthreads();

    // GEMM2 + residual
    {
        const int r0 = tt * 4, c0 = ct * 4;
        float acc[4][4];
        #pragma unroll
        for (int r = 0; r < 4; r++)
            #pragma unroll
            for (int c = 0; c < 4; c++) acc[r][c] = 0.f;
        #pragma unroll 2
        for (int j4 = 0; j4 < H2; j4 += 4) {
            float uv[4][4];
            #pragma unroll
            for (int r = 0; r < 4; r++)
                *(float4*)uv[r] = *(const float4*)&u_sm[(r0 + r) * H2 + j4];
            #pragma unroll
            for (int jj = 0; jj < 4; jj++) {
                float4 w = *(const float4*)&wbuf[(j4 + jj) * HH + c0];
                #pragma unroll
                for (int r = 0; r < 4; r++) {
                    float uvv = uv[r][jj];
                    acc[r][0] = fmaf(uvv, w.x, acc[r][0]);
                    acc[r][1] = fmaf(uvv, w.y, acc[r][1]);
                    acc[r][2] = fmaf(uvv, w.z, acc[r][2]);
                    acc[r][3] = fmaf(uvv, w.w, acc[r][3]);
                }
            }
        }
        #pragma unroll
        for (int r = 0; r < 4; r++)
            #pragma unroll
            for (int c = 0; c < 4; c++)
                h_sm[(r0 + r) * HPAD + c0 + c] += acc[r][c] + b2s[c0 + c];
    }
    __syncthreads();

    // LN (4 threads/token) + load kpW
    {
        const int tq  = tid >> 2;
        const int sub = tid & 3;
        const int j0  = sub * 16;
        float s = 0.f, ss = 0.f;
        #pragma unroll 4
        for (int j = j0; j < j0 + 16; j++) {
            float x = h_sm[tq * HPAD + j];
            s += x; ss += x * x;
        }
        s  += __shfl_xor_sync(0xffffffffu, s, 1);
        ss += __shfl_xor_sync(0xffffffffu, ss, 1);
        s  += __shfl_xor_sync(0xffffffffu, s, 2);
        ss += __shfl_xor_sync(0xffffffffu, ss, 2);
        float mu = s * (1.f / HH);
        float var = ss * (1.f / HH) - mu * mu;
        float rs = rsqrtf(var + 1e-5f);
        #pragma unroll 4
        for (int j = j0; j < j0 + 16; j++) {
            float x = h_sm[tq * HPAD + j];
            h_sm[tq * HPAD + j] = (x - mu) * rs * gsm[j] + bsm[j];
        }
        const float4* w4 = (const float4*)kpW;
        float4* d4 = (float4*)wbuf;
        #pragma unroll
        for (int k = 0; k < 4; k++) d4[tid + 256 * k] = w4[tid + 256 * k];
    }
    __syncthreads();

    // GEMM3 -> g_kall
    {
        const int r0 = tt * 4, c0 = ct * 4;
        float acc[4][4];
        #pragma unroll
        for (int r = 0; r < 4; r++)
            #pragma unroll
            for (int c = 0; c < 4; c++) acc[r][c] = 0.f;
        #pragma unroll 2
        for (int j4 = 0; j4 < HH; j4 += 4) {
            float hv[4][4];
            #pragma unroll
            for (int r = 0; r < 4; r++)
                *(float4*)hv[r] = *(const float4*)&h_sm[(r0 + r) * HPAD + j4];
            #pragma unroll
            for (int jj = 0; jj < 4; jj++) {
                float4 w = *(const float4*)&wbuf[(j4 + jj) * HH + c0];
                #pragma unroll
                for (int r = 0; r < 4; r++) {
                    float hvv = hv[r][jj];
                    acc[r][0] = fmaf(hvv, w.x, acc[r][0]);
                    acc[r][1] = fmaf(hvv, w.y, acc[r][1]);
                    acc[r][2] = fmaf(hvv, w.z, acc[r][2]);
                    acc[r][3] = fmaf(hvv, w.w, acc[r][3]);
                }
            }
        }
        #pragma unroll
        for (int r = 0; r < 4; r++)
            #pragma unroll
            for (int c = 0; c < 4; c++)
                g_kall[(tok0 + r0 + r) * HH + c0 + c] = acc[r][c];
    }
}

// ---------------------------------------------------------------------------
// Kernel 1b: per-(b,t): g_meta = (rinv, 0.16*kk, D1, D2), g_dx = (D3, D4, D5).
// ---------------------------------------------------------------------------
__global__ void k1b_meta() {
    const int g    = blockIdx.x * 8 + (threadIdx.x >> 5);
    const int lane = threadIdx.x & 31;
    const int b = g >> 10, t = g & 1023;
    if (t >= LL - 1) return;
    const float* kt = g_kall + (b * LL + t) * HH;
    float2 k0 = *(const float2*)&kt[lane * 2];
    float2 kv[5];
    #pragma unroll
    for (int s = 1; s <= 5; s++) {
        kv[s - 1] = (t + s <= LL - 1) ? *(const float2*)&kt[s * HH + lane * 2]
                                      : make_float2(0.f, 0.f);
    }
    float pkk = k0.x * k0.x + k0.y * k0.y;
    float pd[5];
    #pragma unroll
    for (int s = 0; s < 5; s++) pd[s] = k0.x * kv[s].x + k0.y * kv[s].y;
    #pragma unroll
    for (int off = 16; off; off >>= 1) {
        pkk += __shfl_xor_sync(0xffffffffu, pkk, off);
        #pragma unroll
        for (int s = 0; s < 5; s++)
            pd[s] += __shfl_xor_sync(0xffffffffu, pd[s], off);
    }
    if (lane == 0) {
        float rinv = 1.0f / fmaxf(sqrtf(pkk), 1e-12f);
        g_meta[b * LL + t] = make_float4(rinv, 0.16f * pkk, pd[0], pd[1]);
        g_dx[b * LL + t]   = make_float4(pd[2], pd[3], pd[4], 0.f);
    }
}

// ---------------------------------------------------------------------------
// Kernel 2: THREE-STEP fused scan. One 6-value Gram butterfly + ONE barrier
// per three steps (1023 = 3*341, no trailing step). Pending updates for
// t-3..t-1 applied under block-uniform conditionals; triple matvec vs
// k^{t+3..t+5} in one M-pass. 16-slot k ring (lag span 12).
// Gate recursion: err1 = e1 - c*err0;  err2 = e2 - a*err0 - b*err1,
// norms evaluated in the (e0,e1,e2) basis from the Gram matrix.
// ---------------------------------------------------------------------------
__global__ void __launch_bounds__(64, 1) k2_scan(const float* __restrict__ rpW,
                                                 const float* __restrict__ rpb) {
    const int b = blockIdx.x;
    const int i = threadIdx.x;
    const int w = i >> 5;
    __shared__ __align__(16) float kbuf[16][64];
    __shared__ __align__(16) float wsum[2][2][8];  // [parity][warp][6 Gram vals]
    __shared__ float rds[64];

    float M[64];
    #pragma unroll
    for (int j = 0; j < 64; j++) M[j] = 0.f;

    const float*  kb = g_kall + b * LL * HH;
    const float4* mb = g_meta + b * LL;
    const float4* db = g_dx  + b * LL;

    #pragma unroll
    for (int sl = 0; sl < 16; sl++) kbuf[sl][i] = 0.f;

    float kc0 = kb[i];
    float kc1 = kb[HH + i];
    float kc2 = kb[2 * HH + i];
    float x0  = kb[3 * HH + i];
    float x1  = kb[4 * HH + i];
    float x2  = kb[5 * HH + i];
    kbuf[0][i] = kc0;  kbuf[1][i] = kc1;  kbuf[2][i] = kc2;
    kbuf[3][i] = x0;   kbuf[4][i] = x1;   kbuf[5][i] = x2;

    float gsA = 0.f, gsB = 0.f, gsC = 0.f;   // gs for steps t-3, t-2, t-1
    int   fA = 0, fB = 0, fC = 0;
    float a0 = 0.f, a1 = 0.f, a2 = 0.f;      // M_{t-4} @ k^{t..t+2}
    // carried dots: cAx=D(t-3,t) cAy=D(t-3,t+1) cAz=D(t-3,t+2)
    //               cBw=D(t-2,t) cBx=D(t-2,t+1) cBy=D(t-2,t+2)
    //               cCz=D(t-1,t) cCw=D(t-1,t+1) cCx=D(t-1,t+2)
    float cAx = 0.f, cAy = 0.f, cAz = 0.f;
    float cBw = 0.f, cBx = 0.f, cBy = 0.f;
    float cCz = 0.f, cCw = 0.f, cCx = 0.f;
    __syncthreads();

    for (int t = 0; t < LL - 1; t += 3) {
        const int par = (t / 3) & 1;
        float4 m0 = mb[t], m1 = mb[t + 1], m2 = mb[t + 2];
        float4 d0 = db[t], d1 = db[t + 1], d2 = db[t + 2];
        float y0 = (t + 6 <= LL - 1) ? kb[(t + 6) * HH + i] : 0.f;
        float y1 = (t + 7 <= LL - 1) ? kb[(t + 7) * HH + i] : 0.f;
        float y2 = (t + 8 <= LL - 1) ? kb[(t + 8) * HH + i] : 0.f;

        // 1. base errors for steps t, t+1, t+2 (critical chain)
        float vpk0 = fmaf(gsA, cAx, fmaf(gsB, cBw, fmaf(gsC, cCz, a0)));
        float e0v  = fmaf(-m0.x, vpk0, kc0);
        float vpk1 = fmaf(gsA, cAy, fmaf(gsB, cBx, fmaf(gsC, cCw, a1)));
        float e1v  = fmaf(-m1.x, vpk1, kc1);
        float vpk2 = fmaf(gsA, cAz, fmaf(gsB, cBy, fmaf(gsC, cCx, a2)));
        float e2v  = fmaf(-m2.x, vpk2, kc2);

        // 2. 6-value Gram butterfly (interleaved chains)
        float p00 = e0v * e0v, p01 = e0v * e1v, p02 = e0v * e2v;
        float p11 = e1v * e1v, p12 = e1v * e2v, p22 = e2v * e2v;
        #pragma unroll
        for (int off = 16; off; off >>= 1) {
            p00 += __shfl_xor_sync(0xffffffffu, p00, off);
            p01 += __shfl_xor_sync(0xffffffffu, p01, off);
            p02 += __shfl_xor_sync(0xffffffffu, p02, off);
            p11 += __shfl_xor_sync(0xffffffffu, p11, off);
            p12 += __shfl_xor_sync(0xffffffffu, p12, off);
            p22 += __shfl_xor_sync(0xffffffffu, p22, off);
        }
        if ((i & 31) == 0) {
            *(float4*)&wsum[par][w][0] = make_float4(p00, p01, p02, p11);
            *(float2*)&wsum[par][w][4] = make_float2(p12, p22);
        }

        // 3. conditional pending updates (block-uniform)
        if (fA) {
            const float* kp = kbuf[(t - 3) & 15];
            #pragma unroll
            for (int j = 0; j < 64; j += 4) {
                float4 k4 = *(const float4*)&kp[j];
                M[j]     = fmaf(gsA, k4.x, M[j]);
                M[j + 1] = fmaf(gsA, k4.y, M[j + 1]);
                M[j + 2] = fmaf(gsA, k4.z, M[j + 2]);
                M[j + 3] = fmaf(gsA, k4.w, M[j + 3]);
            }
        }
        if (fB) {
            const float* kp = kbuf[(t - 2) & 15];
            #pragma unroll
            for (int j = 0; j < 64; j += 4) {
                float4 k4 = *(const float4*)&kp[j];
                M[j]     = fmaf(gsB, k4.x, M[j]);
                M[j + 1] = fmaf(gsB, k4.y, M[j + 1]);
                M[j + 2] = fmaf(gsB, k4.z, M[j + 2]);
                M[j + 3] = fmaf(gsB, k4.w, M[j + 3]);
            }
        }
        if (fC) {
            const float* kp = kbuf[(t - 1) & 15];
            #pragma unroll
            for (int j = 0; j < 64; j += 4) {
                float4 k4 = *(const float4*)&kp[j];
                M[j]     = fmaf(gsC, k4.x, M[j]);
                M[j + 1] = fmaf(gsC, k4.y, M[j + 1]);
                M[j + 2] = fmaf(gsC, k4.z, M[j + 2]);
                M[j + 3] = fmaf(gsC, k4.w, M[j + 3]);
            }
        }

        // 4. publish k^{t+6..t+8}
        kbuf[(t + 6) & 15][i] = y0;
        kbuf[(t + 7) & 15][i] = y1;
        kbuf[(t + 8) & 15][i] = y2;

        // 5. triple matvec: a_s = M_{t-1} @ k^{t+3+s}
        {
            const float* knA = kbuf[(t + 3) & 15];
            const float* knB = kbuf[(t + 4) & 15];
            const float* knC = kbuf[(t + 5) & 15];
            float v0 = 0.f, v1 = 0.f, v2 = 0.f, v3 = 0.f;
            float u0 = 0.f, u1 = 0.f, u2 = 0.f, u3 = 0.f;
            float q0 = 0.f, q1 = 0.f, q2 = 0.f, q3 = 0.f;
            #pragma unroll
            for (int j = 0; j < 64; j += 4) {
                float4 nA = *(const float4*)&knA[j];
                float4 nB = *(const float4*)&knB[j];
                float4 nC = *(const float4*)&knC[j];
                v0 = fmaf(M[j],     nA.x, v0);
                u0 = fmaf(M[j],     nB.x, u0);
                q0 = fmaf(M[j],     nC.x, q0);
                v1 = fmaf(M[j + 1], nA.y, v1);
                u1 = fmaf(M[j + 1], nB.y, u1);
                q1 = fmaf(M[j + 1], nC.y, q1);
                v2 = fmaf(M[j + 2], nA.z, v2);
                u2 = fmaf(M[j + 2], nB.z, u2);
                q2 = fmaf(M[j + 2], nC.z, q2);
                v3 = fmaf(M[j + 3], nA.w, v3);
                u3 = fmaf(M[j + 3], nB.w, u3);
                q3 = fmaf(M[j + 3], nC.w, q3);
            }
            a0 = (v0 + v1) + (v2 + v3);
            a1 = (u0 + u1) + (u2 + u3);
            a2 = (q0 + q1) + (q2 + q3);
        }

        // 6. ONE barrier per three steps; resolve all three gates
        __syncthreads();
        float4 oA = *(const float4*)&wsum[par][w ^ 1][0];
        float2 oB = *(const float2*)&wsum[par][w ^ 1][4];
        float G00 = p00 + oA.x, G01 = p01 + oA.y, G02 = p02 + oA.z;
        float G11 = p11 + oA.w, G12 = p12 + oB.x, G22 = p22 + oB.y;

        int gate0 = G00 >= m0.y;
        float c01 = m1.x * m0.x * m0.z;
        float cg  = gate0 ? c01 : 0.f;
        float n1  = fmaf(cg * cg, G00, G11) - 2.f * cg * G01;
        int gate1 = n1 >= m1.y;
        float alpha = gate0 ? (m2.x * m0.x * m0.w) : 0.f;
        float beta  = gate1 ? (m2.x * m1.x * m1.z) : 0.f;
        float g0c = fmaf(beta, cg, -alpha);   // coeff on e0 in err2
        float g1c = -beta;                    // coeff on e1 in err2
        float n2 = G22 + g1c * g1c * G11 + g0c * g0c * G00
                 + 2.f * (g1c * G12 + g0c * G02 + g0c * g1c * G01);
        int gate2 = n2 >= m2.y;
        float err1 = fmaf(-cg, e0v, e1v);
        float err2 = fmaf(g0c, e0v, fmaf(g1c, e1v, e2v));
        gsA = gate0 ? e0v  * m0.x : 0.f;  fA = gate0;
        gsB = gate1 ? err1 * m1.x : 0.f;  fB = gate1;
        gsC = gate2 ? err2 * m2.x : 0.f;  fC = gate2;

        // carry dots for next group's corrections (and the epilogue)
        cAx = d0.x;  cAy = d0.y;  cAz = d0.z;
        cBw = m1.w;  cBx = d1.x;  cBy = d1.y;
        cCz = m2.z;  cCw = m2.w;  cCx = d2.x;
        // shift k registers
        kc0 = x0; kc1 = x1; kc2 = x2;
        x0 = y0; x1 = y1; x2 = y2;
    }

    // epilogue: read = M_{1022}@q = a0 + gs_{1020}*D(1020,1023)
    //                + gs_{1021}*D(1021,1023) + gs_{1022}*D(1022,1023)
    float readv = fmaf(gsA, cAx, fmaf(gsB, cBw, fmaf(gsC, cCz, a0)));
    rds[i] = readv;
    __syncthreads();

    // r2[b][i] = read . rpW[:, i] + rpb[i]
    float acc = rpb[i];
    #pragma unroll 8
    for (int j = 0; j < 64; j++) acc = fmaf(rds[j], rpW[j * HH + i], acc);
    g_r2[b * HH + i] = acc;
}

// ---------------------------------------------------------------------------
// Kernel 3: out[b][v] (round-13 measured-best: float2, 8 groups x 8 batches)
// ---------------------------------------------------------------------------
__global__ void __launch_bounds__(512, 2) k3_out(const float* __restrict__ outW,
                                                 const float* __restrict__ outb,
                                                 float* __restrict__ out) {
    __shared__ float r2s[64 * 64];
    const int tid = threadIdx.x;
    for (int idx = tid; idx < 64 * 64; idx += 512) r2s[idx] = g_r2[idx];
    __syncthreads();

    const int vl = tid & 63;
    const int g  = tid >> 6;
    const int v2 = blockIdx.x * 64 + vl;
    const int b0 = g * 8;

    const float2* outW2 = (const float2*)outW;
    float2 acc[8];
    #pragma unroll
    for (int bb = 0; bb < 8; bb++) acc[bb] = make_float2(0.f, 0.f);

    #pragma unroll 8
    for (int j = 0; j < 64; j++) {
        float2 wv = outW2[j * (VV / 2) + v2];
        #pragma unroll
        for (int bb = 0; bb < 8; bb++) {
            float r = r2s[(b0 + bb) * 64 + j];
            acc[bb].x = fmaf(r, wv.x, acc[bb].x);
            acc[bb].y = fmaf(r, wv.y, acc[bb].y);
        }
    }
    float2 ob = ((const float2*)outb)[v2];
    float2* out2 = (float2*)out;
    #pragma unroll
    for (int bb = 0; bb < 8; bb++) {
        float2 r = acc[bb];
        r.x += ob.x; r.y += ob.y;
        out2[(b0 + bb) * (VV / 2) + v2] = r;
    }
}

// ---------------------------------------------------------------------------
extern "C" void kernel_launch(void* const* d_in, const int* in_sizes, int n_in,
                              void* d_out, int out_size) {
    const int*   seq   = (const int*)d_in[0];
    const float* embed = (const float*)d_in[1];
    const float* W1    = (const float*)d_in[2];
    const float* b1    = (const float*)d_in[3];
    const float* W2    = (const float*)d_in[4];
    const float* b2    = (const float*)d_in[5];
    const float* gamma = (const float*)d_in[6];
    const float* beta  = (const float*)d_in[7];
    const float* kpW   = (const float*)d_in[8];
    const float* rpW   = (const float*)d_in[9];
    const float* rpb   = (const float*)d_in[10];
    const float* outW  = (const float*)d_in[11];
    const float* outb  = (const float*)d_in[12];
    float* out = (float*)d_out;

    const int smem1 = (TOK * HPAD + TOK * H2 + HH * H2
                       + H2 + 3 * HH) * (int)sizeof(float);
    cudaFuncSetAttribute(k1_frontend, cudaFuncAttributeMaxDynamicSharedMemorySize, smem1);
    cudaFuncSetAttribute(k1_frontend, cudaFuncAttributePreferredSharedMemoryCarveout, 100);

    k1_frontend<<<(BB * LL) / TOK, 256, smem1>>>(seq, embed, W1, b1, W2, b2,
                                                 gamma, beta, kpW);
    k1b_meta<<<(BB * LL) / 8, 256>>>();
    k2_scan<<<BB, 64>>>(rpW, rpb);
    k3_out<<<VV / 128, 512>>>(outW, outb, out);
}